// round 16
// baseline (speedup 1.0000x reference)
#include <cuda_runtime.h>
#include <cuda_bf16.h>
#include <math.h>
#include <float.h>
#include <stdint.h>

#define D    1024
#define H    16
#define HD   64
#define DFF  4096
#define LYR  4
#define SEQ  1024
#define VOC  32000
#define EPSF 1e-5f
#define NEGF (-3.0e38f)

// ---------------- scratch (device globals; no runtime allocation) ----------
__device__ float g_x  [SEQ * D];
__device__ float g_ex [SEQ * D];
__device__ float g_q  [SEQ * D];
__device__ float g_k  [SEQ * D];
__device__ float g_v  [SEQ * D];
__device__ float g_y  [SEQ * D];
__device__ float g_h1 [SEQ * DFF];
__device__ float g_rs [SEQ];
__device__ float g_cos[SEQ * 32];
__device__ float g_sin[SEQ * 32];

// ---------------- helpers ---------------------------------------------------
__device__ __forceinline__ float blockReduce256(float v) {
    __shared__ float sh[8];
    __shared__ float tot;
    int lane = threadIdx.x & 31, wid = threadIdx.x >> 5;
#pragma unroll
    for (int o = 16; o; o >>= 1) v += __shfl_xor_sync(0xffffffffu, v, o);
    if (lane == 0) sh[wid] = v;
    __syncthreads();
    if (wid == 0) {
        float t = (lane < 8) ? sh[lane] : 0.f;
#pragma unroll
        for (int o = 4; o; o >>= 1) t += __shfl_xor_sync(0xffffffffu, t, o);
        if (lane == 0) tot = t;
    }
    __syncthreads();
    return tot;
}

__device__ __forceinline__ uint32_t f2tf(float x) {
    uint32_t r;
    asm("cvt.rna.tf32.f32 %0, %1;" : "=r"(r) : "f"(x));
    return r;
}

__device__ __forceinline__ void mma_tf32(float* c, const uint32_t* a, const uint32_t* b) {
    asm volatile(
        "mma.sync.aligned.m16n8k8.row.col.f32.tf32.tf32.f32 "
        "{%0,%1,%2,%3}, {%4,%5,%6,%7}, {%8,%9}, {%0,%1,%2,%3};"
        : "+f"(c[0]), "+f"(c[1]), "+f"(c[2]), "+f"(c[3])
        : "r"(a[0]), "r"(a[1]), "r"(a[2]), "r"(a[3]), "r"(b[0]), "r"(b[1]));
}

__device__ __forceinline__ void cp16(uint32_t dst, const float* src) {
    asm volatile("cp.async.cg.shared.global [%0], [%1], 16;" :: "r"(dst), "l"(src));
}
#define CP_COMMIT()  asm volatile("cp.async.commit_group;" ::)
#define CP_WAIT1()   asm volatile("cp.async.wait_group 1;" ::)
#define CP_WAIT0()   asm volatile("cp.async.wait_group 0;" ::)

// ---------------- RoPE table (fp64 once; tiny) -------------------------------
__global__ void rope_table_kernel() {
    int i = blockIdx.x * blockDim.x + threadIdx.x;
    int s = i >> 5, j = i & 31;
    double inv = pow(10000.0, -(double)j / 32.0);
    double ang = (double)s * inv;
    g_cos[i] = (float)cos(ang);
    g_sin[i] = (float)sin(ang);
}

// ---------------- embed gather + rms ---------------------------------------
__global__ void embed_rms_kernel(const int* __restrict__ ids,
                                 const float* __restrict__ emb,
                                 float* __restrict__ x, float* __restrict__ ex) {
    int row = blockIdx.x;
    int id  = ids[row];
    float4 v = ((const float4*)(emb + (size_t)id * D))[threadIdx.x];
    float ss = v.x*v.x + v.y*v.y + v.z*v.z + v.w*v.w;
    ss = blockReduce256(ss);
    float r = rsqrtf(ss * (1.0f / D) + EPSF);
    float4 o = make_float4(v.x*r, v.y*r, v.z*r, v.w*r);
    ((float4*)(x  + (size_t)row * D))[threadIdx.x] = o;
    ((float4*)(ex + (size_t)row * D))[threadIdx.x] = o;
}

// ---------------- per-row rms scale ------------------------------------------
__global__ void rs_kernel(const float* __restrict__ in, float* __restrict__ rs) {
    int row = blockIdx.x;
    float4 v = ((const float4*)(in + (size_t)row * D))[threadIdx.x];
    float ss = v.x*v.x + v.y*v.y + v.z*v.z + v.w*v.w;
    ss = blockReduce256(ss);
    if (threadIdx.x == 0) rs[row] = rsqrtf(ss * (1.0f / D) + EPSF);
}

// ---------------- RoPE + per-head rms, fused q & k ---------------------------
__global__ void rope_rms_kernel(float* __restrict__ qv, float* __restrict__ kv,
                                const float* __restrict__ gain, int l) {
    int s = blockIdx.x, h = blockIdx.y;
    int t = threadIdx.x;
    __shared__ float buf[HD];
    __shared__ float red[2];
    float* p = (blockIdx.z == 0 ? qv : kv) + (size_t)s * D + h * HD;
    buf[t] = p[t];
    __syncthreads();
    int j = t & 31;
    float c  = g_cos[s * 32 + j];
    float sn = g_sin[s * 32 + j];
    float o;
    if (t < 32) o =  buf[t] * c       + buf[t + 32] * sn;
    else        o = -buf[t - 32] * sn + buf[t] * c;
    float ss = o * o;
#pragma unroll
    for (int off = 16; off; off >>= 1) ss += __shfl_xor_sync(0xffffffffu, ss, off);
    if ((t & 31) == 0) red[t >> 5] = ss;
    __syncthreads();
    float tot = red[0] + red[1];
    float r = rsqrtf(tot * (1.0f / HD) + EPSF);
    float g = (blockIdx.z == 0) ? gain[l * H + h] : 1.0f;
    p[t] = o * r * g;
}

// ---------------- TF32 GEMM v4: cp.async 3-stage, epilogue rms scale --------
// A: MxK rm, B: NxK rm. C = epilogue(diag(rs)*A @ B^T)
// EPI: 0 -> g*acc ; 1 -> res + g*acc ; 2 -> res + g*acc + (*skip)*res2
template <int BM, int BN, int EPI, bool SCALE>
__device__ __forceinline__ void gemm4_body(
        const float* __restrict__ A, const float* __restrict__ B,
        float* __restrict__ C, int N, int K,
        const float* __restrict__ res, const float* __restrict__ gainPtr,
        const float* __restrict__ res2, const float* __restrict__ skipPtr,
        const float* __restrict__ rs, int bx, int by) {
    constexpr int WM = (BM == 128 && BN == 64) ? 4 : 2;
    constexpr int WN = 8 / WM;
    constexpr int MT = BM / WM / 16;
    constexpr int NT = BN / WN / 8;
    constexpr int LDR = 36;
    constexpr int ACH = BM / 32;
    constexpr int BCH = BN / 32;
    constexpr int STG_A = BM * LDR;
    constexpr int STG = STG_A + BN * LDR;

    extern __shared__ float sm[];
    const int tid = threadIdx.x, warp = tid >> 5, lane = tid & 31;
    const int wm = warp / WN, wn = warp % WN;
    const int lr = tid >> 3;
    const int lc = (tid & 7) << 2;

    const float* Ab = A + (size_t)(by * BM + lr) * K + lc;
    const float* Bb = B + (size_t)(bx * BN + lr) * K + lc;
    const uint32_t smb = (uint32_t)__cvta_generic_to_shared(sm);
    const uint32_t da0 = smb + (uint32_t)(lr * LDR + lc) * 4u;
    const uint32_t db0 = da0 + (uint32_t)STG_A * 4u;

    auto issue = [&](int tile, int stg) {
        const float* ap = Ab + tile * 32;
        const float* bp = Bb + tile * 32;
        uint32_t da = da0 + (uint32_t)(stg * STG) * 4u;
        uint32_t db = db0 + (uint32_t)(stg * STG) * 4u;
#pragma unroll
        for (int i = 0; i < ACH; i++)
            cp16(da + i * 32 * LDR * 4, ap + (size_t)i * 32 * K);
#pragma unroll
        for (int i = 0; i < BCH; i++)
            cp16(db + i * 32 * LDR * 4, bp + (size_t)i * 32 * K);
        CP_COMMIT();
    };

    float acc[MT][NT][4];
#pragma unroll
    for (int mt = 0; mt < MT; mt++)
#pragma unroll
        for (int nt = 0; nt < NT; nt++)
#pragma unroll
            for (int i = 0; i < 4; i++) acc[mt][nt][i] = 0.f;

    issue(0, 0);
    issue(1, 1);

    const int ntiles = K >> 5;
    const int abase0 = (wm * MT * 16 + (lane >> 2)) * LDR + (lane & 3);
    const int bbase0 = (wn * NT * 8  + (lane >> 2)) * LDR + (lane & 3);

    for (int t = 0; t < ntiles; t++) {
        if (t + 1 < ntiles) { CP_WAIT1(); } else { CP_WAIT0(); }
        __syncthreads();
        if (t + 2 < ntiles) issue(t + 2, (t + 2) % 3);

        const float* as = sm + (t % 3) * STG;
        const float* bs = as + STG_A;
#pragma unroll
        for (int kk = 0; kk < 4; kk++) {
            uint32_t af[MT][4];
#pragma unroll
            for (int mt = 0; mt < MT; mt++) {
                int o = abase0 + mt * 16 * LDR + kk * 8;
                af[mt][0] = f2tf(as[o]);
                af[mt][1] = f2tf(as[o + 8 * LDR]);
                af[mt][2] = f2tf(as[o + 4]);
                af[mt][3] = f2tf(as[o + 8 * LDR + 4]);
            }
            uint32_t bf[NT][2];
#pragma unroll
            for (int nt = 0; nt < NT; nt++) {
                int o = bbase0 + nt * 8 * LDR + kk * 8;
                bf[nt][0] = f2tf(bs[o]);
                bf[nt][1] = f2tf(bs[o + 4]);
            }
#pragma unroll
            for (int mt = 0; mt < MT; mt++)
#pragma unroll
                for (int nt = 0; nt < NT; nt++)
                    mma_tf32(acc[mt][nt], af[mt], bf[nt]);
        }
    }

    const float g = gainPtr ? *gainPtr : 1.0f;
    float sk = 0.f;
    if (EPI == 2) sk = *skipPtr;
    const int r = lane >> 2, c = lane & 3;
#pragma unroll
    for (int mt = 0; mt < MT; mt++) {
        int row0 = by * BM + (wm * MT + mt) * 16 + r;
        float g0 = g, g1 = g;
        if (SCALE) { g0 = g * rs[row0]; g1 = g * rs[row0 + 8]; }
#pragma unroll
        for (int nt = 0; nt < NT; nt++) {
            int col = bx * BN + (wn * NT + nt) * 8 + c * 2;
            size_t i0 = (size_t)row0 * N + col;
            size_t i1 = (size_t)(row0 + 8) * N + col;
            float2 v0 = make_float2(g0 * acc[mt][nt][0], g0 * acc[mt][nt][1]);
            float2 v1 = make_float2(g1 * acc[mt][nt][2], g1 * acc[mt][nt][3]);
            if (EPI >= 1) {
                float2 r0 = *(const float2*)(res + i0);
                float2 r1 = *(const float2*)(res + i1);
                v0.x += r0.x; v0.y += r0.y;
                v1.x += r1.x; v1.y += r1.y;
            }
            if (EPI == 2) {
                float2 e0 = *(const float2*)(res2 + i0);
                float2 e1 = *(const float2*)(res2 + i1);
                v0.x += sk * e0.x; v0.y += sk * e0.y;
                v1.x += sk * e1.x; v1.y += sk * e1.y;
            }
            *(float2*)(C + i0) = v0;
            *(float2*)(C + i1) = v1;
        }
    }
}

template <int BM, int BN, int EPI, bool SCALE, int MINB>
__global__ void __launch_bounds__(256, MINB)
gemm4k(const float* __restrict__ A, const float* __restrict__ B,
       float* __restrict__ C, int N, int K,
       const float* __restrict__ res, const float* __restrict__ gainPtr,
       const float* __restrict__ res2, const float* __restrict__ skipPtr,
       const float* __restrict__ rs) {
    gemm4_body<BM, BN, EPI, SCALE>(A, B, C, N, K, res, gainPtr, res2, skipPtr,
                                   rs, blockIdx.x, blockIdx.y);
}

// fused Q/K/V, 128x128 tiles (MT=4,NT=4 -> 3:1 scalar:MMA); rs in epilogue
__global__ void __launch_bounds__(256, 2)
qkv5(const float* __restrict__ A,
     const float* __restrict__ Wq, const float* __restrict__ Wk,
     const float* __restrict__ Wv, const float* __restrict__ rs,
     float* __restrict__ Cq, float* __restrict__ Ck, float* __restrict__ Cv) {
    const float* B;
    float* C;
    if (blockIdx.z == 0)      { B = Wq; C = Cq; }
    else if (blockIdx.z == 1) { B = Wk; C = Ck; }
    else                      { B = Wv; C = Cv; }
    gemm4_body<128, 128, 0, true>(A, B, C, D, D, nullptr, nullptr, nullptr,
                                  nullptr, rs, blockIdx.x, blockIdx.y);
}

// ---------------- fused gate+linear+silu, BM=128/BN=64 per matrix -----------
// h = silu(rs*A@Wg^T) * (rs*A@Wl^T). MT=4, NT=2 each -> 16 MMAs per kk.
__global__ void __launch_bounds__(256, 2)
gl5(const float* __restrict__ A,
    const float* __restrict__ Wg, const float* __restrict__ Wl,
    float* __restrict__ Ch, const float* __restrict__ rs) {
    constexpr int BM = 128, BN = 64;
    constexpr int WN = 4;
    constexpr int MT = 4, NT = 2;
    constexpr int LDR = 36;
    constexpr int STG_A = BM * LDR;
    constexpr int STG_B = BN * LDR;
    constexpr int STG = STG_A + 2 * STG_B;
    const int K = D, N = DFF;

    extern __shared__ float sm[];
    const int tid = threadIdx.x, warp = tid >> 5, lane = tid & 31;
    const int wm = warp / WN, wn = warp % WN;
    const int lr = tid >> 3, lc = (tid & 7) << 2;
    const int bx = blockIdx.x, by = blockIdx.y;

    const float* Ab = A  + (size_t)(by * BM + lr) * K + lc;
    const float* Gb = Wg + (size_t)(bx * BN + lr) * K + lc;
    const float* Lb = Wl + (size_t)(bx * BN + lr) * K + lc;
    const uint32_t smb = (uint32_t)__cvta_generic_to_shared(sm);
    const uint32_t d0 = smb + (uint32_t)(lr * LDR + lc) * 4u;

    auto issue = [&](int tile, int stg) {
        uint32_t base = d0 + (uint32_t)(stg * STG) * 4u;
#pragma unroll
        for (int i = 0; i < 4; i++)
            cp16(base + i * 32 * LDR * 4, Ab + (size_t)tile * 32 + (size_t)i * 32 * K);
#pragma unroll
        for (int i = 0; i < 2; i++) {
            cp16(base + (STG_A + i * 32 * LDR) * 4,         Gb + (size_t)tile * 32 + (size_t)i * 32 * K);
            cp16(base + (STG_A + STG_B + i * 32 * LDR) * 4, Lb + (size_t)tile * 32 + (size_t)i * 32 * K);
        }
        CP_COMMIT();
    };

    float accg[MT][NT][4], accl[MT][NT][4];
#pragma unroll
    for (int mt = 0; mt < MT; mt++)
#pragma unroll
        for (int nt = 0; nt < NT; nt++)
#pragma unroll
            for (int i = 0; i < 4; i++) { accg[mt][nt][i] = 0.f; accl[mt][nt][i] = 0.f; }

    issue(0, 0);
    issue(1, 1);

    const int ntiles = K >> 5;
    const int abase0 = (wm * MT * 16 + (lane >> 2)) * LDR + (lane & 3);
    const int bbase0 = (wn * NT * 8  + (lane >> 2)) * LDR + (lane & 3);

    for (int t = 0; t < ntiles; t++) {
        if (t + 1 < ntiles) { CP_WAIT1(); } else { CP_WAIT0(); }
        __syncthreads();
        if (t + 2 < ntiles) issue(t + 2, (t + 2) % 3);

        const float* as = sm + (t % 3) * STG;
        const float* gs = as + STG_A;
        const float* ls = gs + STG_B;
#pragma unroll
        for (int kk = 0; kk < 4; kk++) {
            uint32_t af[MT][4];
#pragma unroll
            for (int mt = 0; mt < MT; mt++) {
                int o = abase0 + mt * 16 * LDR + kk * 8;
                af[mt][0] = f2tf(as[o]);
                af[mt][1] = f2tf(as[o + 8 * LDR]);
                af[mt][2] = f2tf(as[o + 4]);
                af[mt][3] = f2tf(as[o + 8 * LDR + 4]);
            }
            uint32_t gf[NT][2], lf[NT][2];
#pragma unroll
            for (int nt = 0; nt < NT; nt++) {
                int o = bbase0 + nt * 8 * LDR + kk * 8;
                gf[nt][0] = f2tf(gs[o]); gf[nt][1] = f2tf(gs[o + 4]);
                lf[nt][0] = f2tf(ls[o]); lf[nt][1] = f2tf(ls[o + 4]);
            }
#pragma unroll
            for (int mt = 0; mt < MT; mt++)
#pragma unroll
                for (int nt = 0; nt < NT; nt++) {
                    mma_tf32(accg[mt][nt], af[mt], gf[nt]);
                    mma_tf32(accl[mt][nt], af[mt], lf[nt]);
                }
        }
    }

    const int r = lane >> 2, c = lane & 3;
#pragma unroll
    for (int mt = 0; mt < MT; mt++) {
        int row0 = by * BM + (wm * MT + mt) * 16 + r;
        float s0 = rs[row0], s1 = rs[row0 + 8];
#pragma unroll
        for (int nt = 0; nt < NT; nt++) {
            int col = bx * BN + (wn * NT + nt) * 8 + c * 2;
#pragma unroll
            for (int half = 0; half < 2; half++) {
                size_t idx = (size_t)(row0 + half * 8) * N + col;
                float s = half ? s1 : s0;
                float gv0 = accg[mt][nt][half * 2 + 0] * s;
                float gv1 = accg[mt][nt][half * 2 + 1] * s;
                float lv0 = accl[mt][nt][half * 2 + 0] * s;
                float lv1 = accl[mt][nt][half * 2 + 1] * s;
                float h0 = gv0 / (1.0f + expf(-gv0)) * lv0;
                float h1 = gv1 / (1.0f + expf(-gv1)) * lv1;
                *(float2*)(Ch + idx) = make_float2(h0, h1);
            }
        }
    }
}

// ---------------- fused causal attention (online softmax, exact fp32) -------
__global__ void __launch_bounds__(256)
attn_kernel(const float* __restrict__ q, const float* __restrict__ k,
            const float* __restrict__ v, float* __restrict__ y) {
    const int h  = blockIdx.x;
    const int q0 = blockIdx.y * 64;
    __shared__ float Qs[64][64];
    __shared__ float Ks[64][32];
    __shared__ float Vs[32][64];
    __shared__ float Ss[64][33];
    __shared__ float mS[64], lS[64], aS[64];
    int tid = threadIdx.x;
    int tx = tid & 15, ty = tid >> 4;

    {
        int r  = tid >> 2;
        int d0 = (tid & 3) << 4;
        const float* src = q + (size_t)(q0 + r) * D + h * HD + d0;
#pragma unroll
        for (int i = 0; i < 16; i += 4) {
            float4 t4 = *(const float4*)(src + i);
            Qs[d0 + i + 0][r] = t4.x; Qs[d0 + i + 1][r] = t4.y;
            Qs[d0 + i + 2][r] = t4.z; Qs[d0 + i + 3][r] = t4.w;
        }
    }
    if (tid < 64) { mS[tid] = NEGF; lS[tid] = 0.f; }
    float acc[4][4];
#pragma unroll
    for (int i = 0; i < 4; i++)
#pragma unroll
        for (int jj = 0; jj < 4; jj++) acc[i][jj] = 0.f;
    __syncthreads();

    const int nk = q0 + 64;
    for (int k0 = 0; k0 < nk; k0 += 32) {
        {
            int kr = tid >> 3;
            int d0 = (tid & 7) << 3;
            const float* ks = k + (size_t)(k0 + kr) * D + h * HD + d0;
            float4 t0 = *(const float4*)ks;
            float4 t1 = *(const float4*)(ks + 4);
            Ks[d0 + 0][kr] = t0.x; Ks[d0 + 1][kr] = t0.y; Ks[d0 + 2][kr] = t0.z; Ks[d0 + 3][kr] = t0.w;
            Ks[d0 + 4][kr] = t1.x; Ks[d0 + 5][kr] = t1.y; Ks[d0 + 6][kr] = t1.z; Ks[d0 + 7][kr] = t1.w;
            const float* vsp = v + (size_t)(k0 + kr) * D + h * HD + d0;
            *(float4*)&Vs[kr][d0]     = *(const float4*)vsp;
            *(float4*)&Vs[kr][d0 + 4] = *(const float4*)(vsp + 4);
        }
        __syncthreads();

        float sc[4][2];
#pragma unroll
        for (int i = 0; i < 4; i++) { sc[i][0] = 0.f; sc[i][1] = 0.f; }
#pragma unroll 16
        for (int d = 0; d < 64; d++) {
            float4 qa = *(const float4*)&Qs[d][ty << 2];
            float2 kb = *(const float2*)&Ks[d][tx << 1];
            sc[0][0] = fmaf(qa.x, kb.x, sc[0][0]); sc[0][1] = fmaf(qa.x, kb.y, sc[0][1]);
            sc[1][0] = fmaf(qa.y, kb.x, sc[1][0]); sc[1][1] = fmaf(qa.y, kb.y, sc[1][1]);
            sc[2][0] = fmaf(qa.z, kb.x, sc[2][0]); sc[2][1] = fmaf(qa.z, kb.y, sc[2][1]);
            sc[3][0] = fmaf(qa.w, kb.x, sc[3][0]); sc[3][1] = fmaf(qa.w, kb.y, sc[3][1]);
        }
#pragma unroll
        for (int i = 0; i < 4; i++) {
            int qg = q0 + (ty << 2) + i;
#pragma unroll
            for (int jj = 0; jj < 2; jj++) {
                int kg = k0 + (tx << 1) + jj;
                float val = sc[i][jj] * 0.125f;
                if (kg > qg) val = NEGF;
                Ss[(ty << 2) + i][(tx << 1) + jj] = val;
            }
        }
        __syncthreads();

        if (tid < 64) {
            float mo = mS[tid];
            float mx = mo;
#pragma unroll
            for (int jj = 0; jj < 32; jj++) mx = fmaxf(mx, Ss[tid][jj]);
            float al = expf(mo - mx);
            float sum = 0.f;
#pragma unroll
            for (int jj = 0; jj < 32; jj++) {
                float pp = expf(Ss[tid][jj] - mx);
                Ss[tid][jj] = pp;
                sum += pp;
            }
            lS[tid] = lS[tid] * al + sum;
            mS[tid] = mx;
            aS[tid] = al;
        }
        __syncthreads();

#pragma unroll
        for (int i = 0; i < 4; i++) {
            float al = aS[(ty << 2) + i];
#pragma unroll
            for (int jj = 0; jj < 4; jj++) acc[i][jj] *= al;
        }
#pragma unroll 8
        for (int kk = 0; kk < 32; kk++) {
            float4 vb = *(const float4*)&Vs[kk][tx << 2];
            float p0 = Ss[(ty << 2) + 0][kk];
            float p1 = Ss[(ty << 2) + 1][kk];
            float p2 = Ss[(ty << 2) + 2][kk];
            float p3 = Ss[(ty << 2) + 3][kk];
            acc[0][0] = fmaf(p0, vb.x, acc[0][0]); acc[0][1] = fmaf(p0, vb.y, acc[0][1]);
            acc[0][2] = fmaf(p0, vb.z, acc[0][2]); acc[0][3] = fmaf(p0, vb.w, acc[0][3]);
            acc[1][0] = fmaf(p1, vb.x, acc[1][0]); acc[1][1] = fmaf(p1, vb.y, acc[1][1]);
            acc[1][2] = fmaf(p1, vb.z, acc[1][2]); acc[1][3] = fmaf(p1, vb.w, acc[1][3]);
            acc[2][0] = fmaf(p2, vb.x, acc[2][0]); acc[2][1] = fmaf(p2, vb.y, acc[2][1]);
            acc[2][2] = fmaf(p2, vb.z, acc[2][2]); acc[2][3] = fmaf(p2, vb.w, acc[2][3]);
            acc[3][0] = fmaf(p3, vb.x, acc[3][0]); acc[3][1] = fmaf(p3, vb.y, acc[3][1]);
            acc[3][2] = fmaf(p3, vb.z, acc[3][2]); acc[3][3] = fmaf(p3, vb.w, acc[3][3]);
        }
        __syncthreads();
    }

#pragma unroll
    for (int i = 0; i < 4; i++) {
        float linv = 1.0f / lS[(ty << 2) + i];
        float4 o = make_float4(acc[i][0] * linv, acc[i][1] * linv,
                               acc[i][2] * linv, acc[i][3] * linv);
        *(float4*)(y + (size_t)(q0 + (ty << 2) + i) * D + h * HD + (tx << 2)) = o;
    }
}

// ---------------- launch -----------------------------------------------------
extern "C" void kernel_launch(void* const* d_in, const int* in_sizes, int n_in,
                              void* d_out, int out_size) {
    const int*   ids          = (const int*)  d_in[0];
    const float* embed        = (const float*)d_in[1];
    const float* Wq           = (const float*)d_in[2];
    const float* Wk           = (const float*)d_in[3];
    const float* Wv           = (const float*)d_in[4];
    const float* Wo           = (const float*)d_in[5];
    const float* head_gain    = (const float*)d_in[6];
    const float* attn_gain    = (const float*)d_in[7];
    const float* Wg           = (const float*)d_in[8];
    const float* Wl           = (const float*)d_in[9];
    const float* Wr           = (const float*)d_in[10];
    const float* mlp_gain     = (const float*)d_in[11];
    const float* embed_skip   = (const float*)d_in[12];
    const float* lm_head      = (const float*)d_in[13];
    const float* lm_head_gain = (const float*)d_in[14];
    float* out = (float*)d_out;

    float *px, *pex, *pq, *pk, *pv, *py, *ph1, *prs;
    cudaGetSymbolAddress((void**)&px,  g_x);
    cudaGetSymbolAddress((void**)&pex, g_ex);
    cudaGetSymbolAddress((void**)&pq,  g_q);
    cudaGetSymbolAddress((void**)&pk,  g_k);
    cudaGetSymbolAddress((void**)&pv,  g_v);
    cudaGetSymbolAddress((void**)&py,  g_y);
    cudaGetSymbolAddress((void**)&ph1, g_h1);
    cudaGetSymbolAddress((void**)&prs, g_rs);

    const int SM_S  = 3 * (64 + 64)   * 36 * 4;   // 55296
    const int SM_BB = 3 * (128 + 128) * 36 * 4;   // 110592 (qkv / gl / lm_head)

    cudaFuncSetAttribute(qkv5, cudaFuncAttributeMaxDynamicSharedMemorySize, SM_BB);
    cudaFuncSetAttribute(gl5,  cudaFuncAttributeMaxDynamicSharedMemorySize, SM_BB);
    cudaFuncSetAttribute(gemm4k<64, 64, 1, false, 3>, cudaFuncAttributeMaxDynamicSharedMemorySize, SM_S);
    cudaFuncSetAttribute(gemm4k<64, 64, 2, false, 3>, cudaFuncAttributeMaxDynamicSharedMemorySize, SM_S);
    cudaFuncSetAttribute(gemm4k<128, 128, 0, true, 2>, cudaFuncAttributeMaxDynamicSharedMemorySize, SM_BB);

    rope_table_kernel<<<(SEQ * 32) / 256, 256>>>();
    embed_rms_kernel<<<SEQ, 256>>>(ids, embed, px, pex);

    dim3 gQKV(D / 128, SEQ / 128, 3);      // 192 blocks
    dim3 gOW (D / 64, SEQ / 64);           // 256 blocks
    dim3 gGL (DFF / 64, SEQ / 128);        // 512 blocks
    dim3 gLM (VOC / 128, SEQ / 128);       // 2000 blocks
    dim3 gRope(SEQ, H, 2);
    dim3 gAttn(H, SEQ / 64);

    for (int l = 0; l < LYR; l++) {
        rs_kernel<<<SEQ, 256>>>(px, prs);
        qkv5<<<gQKV, 256, SM_BB>>>(px, Wq + (size_t)l * D * D, Wk + (size_t)l * D * D,
                                   Wv + (size_t)l * D * D, prs, pq, pk, pv);
        rope_rms_kernel<<<gRope, 64>>>(pq, pk, head_gain, l);
        attn_kernel<<<gAttn, 256>>>(pq, pk, pv, py);
        gemm4k<64, 64, 1, false, 3><<<gOW, 256, SM_S>>>(
            py, Wo + (size_t)l * D * D, px, D, D, px, attn_gain + l,
            nullptr, nullptr, nullptr);
        rs_kernel<<<SEQ, 256>>>(px, prs);
        gl5<<<gGL, 256, SM_BB>>>(px, Wg + (size_t)l * DFF * D,
                                 Wl + (size_t)l * DFF * D, ph1, prs);
        gemm4k<64, 64, 2, false, 3><<<gOW, 256, SM_S>>>(
            ph1, Wr + (size_t)l * D * DFF, px, D, DFF, px, mlp_gain + l,
            pex, embed_skip + l, nullptr);
    }

    rs_kernel<<<SEQ, 256>>>(px, prs);
    gemm4k<128, 128, 0, true, 2><<<gLM, 256, SM_BB>>>(
        px, lm_head, out, VOC, D, nullptr, lm_head_gain, nullptr, nullptr, prs);
}

// round 17
// speedup vs baseline: 1.0103x; 1.0103x over previous
#include <cuda_runtime.h>
#include <cuda_bf16.h>
#include <math.h>
#include <float.h>
#include <stdint.h>

#define D    1024
#define H    16
#define HD   64
#define DFF  4096
#define LYR  4
#define SEQ  1024
#define VOC  32000
#define EPSF 1e-5f
#define NEGF (-3.0e38f)

// ---------------- scratch (device globals; no runtime allocation) ----------
__device__ float g_x  [SEQ * D];
__device__ float g_ex [SEQ * D];
__device__ float g_q  [SEQ * D];
__device__ float g_k  [SEQ * D];
__device__ float g_v  [SEQ * D];
__device__ float g_y  [SEQ * D];
__device__ float g_h1 [SEQ * DFF];
__device__ float g_rs [SEQ];
__device__ float g_cos[SEQ * 32];
__device__ float g_sin[SEQ * 32];

// ---------------- helpers ---------------------------------------------------
__device__ __forceinline__ float blockReduce256(float v) {
    __shared__ float sh[8];
    __shared__ float tot;
    int lane = threadIdx.x & 31, wid = threadIdx.x >> 5;
#pragma unroll
    for (int o = 16; o; o >>= 1) v += __shfl_xor_sync(0xffffffffu, v, o);
    if (lane == 0) sh[wid] = v;
    __syncthreads();
    if (wid == 0) {
        float t = (lane < 8) ? sh[lane] : 0.f;
#pragma unroll
        for (int o = 4; o; o >>= 1) t += __shfl_xor_sync(0xffffffffu, t, o);
        if (lane == 0) tot = t;
    }
    __syncthreads();
    return tot;
}

__device__ __forceinline__ uint32_t f2tf(float x) {
    uint32_t r;
    asm("cvt.rna.tf32.f32 %0, %1;" : "=r"(r) : "f"(x));
    return r;
}

__device__ __forceinline__ void mma_tf32(float* c, const uint32_t* a, const uint32_t* b) {
    asm volatile(
        "mma.sync.aligned.m16n8k8.row.col.f32.tf32.tf32.f32 "
        "{%0,%1,%2,%3}, {%4,%5,%6,%7}, {%8,%9}, {%0,%1,%2,%3};"
        : "+f"(c[0]), "+f"(c[1]), "+f"(c[2]), "+f"(c[3])
        : "r"(a[0]), "r"(a[1]), "r"(a[2]), "r"(a[3]), "r"(b[0]), "r"(b[1]));
}

__device__ __forceinline__ void cp16(uint32_t dst, const float* src) {
    asm volatile("cp.async.cg.shared.global [%0], [%1], 16;" :: "r"(dst), "l"(src));
}
#define CP_COMMIT()  asm volatile("cp.async.commit_group;" ::)
#define CP_WAIT1()   asm volatile("cp.async.wait_group 1;" ::)
#define CP_WAIT0()   asm volatile("cp.async.wait_group 0;" ::)

// ---------------- RoPE table (fp64 once; tiny) -------------------------------
__global__ void rope_table_kernel() {
    int i = blockIdx.x * blockDim.x + threadIdx.x;
    int s = i >> 5, j = i & 31;
    double inv = pow(10000.0, -(double)j / 32.0);
    double ang = (double)s * inv;
    g_cos[i] = (float)cos(ang);
    g_sin[i] = (float)sin(ang);
}

// ---------------- embed gather + rms ---------------------------------------
__global__ void embed_rms_kernel(const int* __restrict__ ids,
                                 const float* __restrict__ emb,
                                 float* __restrict__ x, float* __restrict__ ex) {
    int row = blockIdx.x;
    int id  = ids[row];
    float4 v = ((const float4*)(emb + (size_t)id * D))[threadIdx.x];
    float ss = v.x*v.x + v.y*v.y + v.z*v.z + v.w*v.w;
    ss = blockReduce256(ss);
    float r = rsqrtf(ss * (1.0f / D) + EPSF);
    float4 o = make_float4(v.x*r, v.y*r, v.z*r, v.w*r);
    ((float4*)(x  + (size_t)row * D))[threadIdx.x] = o;
    ((float4*)(ex + (size_t)row * D))[threadIdx.x] = o;
}

// ---------------- per-row rms scale ------------------------------------------
__global__ void rs_kernel(const float* __restrict__ in, float* __restrict__ rs) {
    int row = blockIdx.x;
    float4 v = ((const float4*)(in + (size_t)row * D))[threadIdx.x];
    float ss = v.x*v.x + v.y*v.y + v.z*v.z + v.w*v.w;
    ss = blockReduce256(ss);
    if (threadIdx.x == 0) rs[row] = rsqrtf(ss * (1.0f / D) + EPSF);
}

// ---------------- RoPE + per-head rms, fused q & k ---------------------------
__global__ void rope_rms_kernel(float* __restrict__ qv, float* __restrict__ kv,
                                const float* __restrict__ gain, int l) {
    int s = blockIdx.x, h = blockIdx.y;
    int t = threadIdx.x;
    __shared__ float buf[HD];
    __shared__ float red[2];
    float* p = (blockIdx.z == 0 ? qv : kv) + (size_t)s * D + h * HD;
    buf[t] = p[t];
    __syncthreads();
    int j = t & 31;
    float c  = g_cos[s * 32 + j];
    float sn = g_sin[s * 32 + j];
    float o;
    if (t < 32) o =  buf[t] * c       + buf[t + 32] * sn;
    else        o = -buf[t - 32] * sn + buf[t] * c;
    float ss = o * o;
#pragma unroll
    for (int off = 16; off; off >>= 1) ss += __shfl_xor_sync(0xffffffffu, ss, off);
    if ((t & 31) == 0) red[t >> 5] = ss;
    __syncthreads();
    float tot = red[0] + red[1];
    float r = rsqrtf(tot * (1.0f / HD) + EPSF);
    float g = (blockIdx.z == 0) ? gain[l * H + h] : 1.0f;
    p[t] = o * r * g;
}

// ---------------- TF32 GEMM v4: cp.async 3-stage, epilogue rms scale --------
// A: MxK rm, B: NxK rm. C = epilogue(diag(rs)*A @ B^T)
// EPI: 0 -> g*acc ; 1 -> res + g*acc ; 2 -> res + g*acc + (*skip)*res2
template <int BM, int BN, int EPI, bool SCALE>
__device__ __forceinline__ void gemm4_body(
        const float* __restrict__ A, const float* __restrict__ B,
        float* __restrict__ C, int N, int K,
        const float* __restrict__ res, const float* __restrict__ gainPtr,
        const float* __restrict__ res2, const float* __restrict__ skipPtr,
        const float* __restrict__ rs, int bx, int by) {
    constexpr int WM = (BM == 128 && BN == 64) ? 4 : 2;
    constexpr int WN = 8 / WM;
    constexpr int MT = BM / WM / 16;
    constexpr int NT = BN / WN / 8;
    constexpr int LDR = 36;
    constexpr int ACH = BM / 32;
    constexpr int BCH = BN / 32;
    constexpr int STG_A = BM * LDR;
    constexpr int STG = STG_A + BN * LDR;

    extern __shared__ float sm[];
    const int tid = threadIdx.x, warp = tid >> 5, lane = tid & 31;
    const int wm = warp / WN, wn = warp % WN;
    const int lr = tid >> 3;
    const int lc = (tid & 7) << 2;

    const float* Ab = A + (size_t)(by * BM + lr) * K + lc;
    const float* Bb = B + (size_t)(bx * BN + lr) * K + lc;
    const uint32_t smb = (uint32_t)__cvta_generic_to_shared(sm);
    const uint32_t da0 = smb + (uint32_t)(lr * LDR + lc) * 4u;
    const uint32_t db0 = da0 + (uint32_t)STG_A * 4u;

    auto issue = [&](int tile, int stg) {
        const float* ap = Ab + tile * 32;
        const float* bp = Bb + tile * 32;
        uint32_t da = da0 + (uint32_t)(stg * STG) * 4u;
        uint32_t db = db0 + (uint32_t)(stg * STG) * 4u;
#pragma unroll
        for (int i = 0; i < ACH; i++)
            cp16(da + i * 32 * LDR * 4, ap + (size_t)i * 32 * K);
#pragma unroll
        for (int i = 0; i < BCH; i++)
            cp16(db + i * 32 * LDR * 4, bp + (size_t)i * 32 * K);
        CP_COMMIT();
    };

    float acc[MT][NT][4];
#pragma unroll
    for (int mt = 0; mt < MT; mt++)
#pragma unroll
        for (int nt = 0; nt < NT; nt++)
#pragma unroll
            for (int i = 0; i < 4; i++) acc[mt][nt][i] = 0.f;

    issue(0, 0);
    issue(1, 1);

    const int ntiles = K >> 5;
    const int abase0 = (wm * MT * 16 + (lane >> 2)) * LDR + (lane & 3);
    const int bbase0 = (wn * NT * 8  + (lane >> 2)) * LDR + (lane & 3);

    for (int t = 0; t < ntiles; t++) {
        if (t + 1 < ntiles) { CP_WAIT1(); } else { CP_WAIT0(); }
        __syncthreads();
        if (t + 2 < ntiles) issue(t + 2, (t + 2) % 3);

        const float* as = sm + (t % 3) * STG;
        const float* bs = as + STG_A;
#pragma unroll
        for (int kk = 0; kk < 4; kk++) {
            uint32_t af[MT][4];
#pragma unroll
            for (int mt = 0; mt < MT; mt++) {
                int o = abase0 + mt * 16 * LDR + kk * 8;
                af[mt][0] = f2tf(as[o]);
                af[mt][1] = f2tf(as[o + 8 * LDR]);
                af[mt][2] = f2tf(as[o + 4]);
                af[mt][3] = f2tf(as[o + 8 * LDR + 4]);
            }
            uint32_t bf[NT][2];
#pragma unroll
            for (int nt = 0; nt < NT; nt++) {
                int o = bbase0 + nt * 8 * LDR + kk * 8;
                bf[nt][0] = f2tf(bs[o]);
                bf[nt][1] = f2tf(bs[o + 4]);
            }
#pragma unroll
            for (int mt = 0; mt < MT; mt++)
#pragma unroll
                for (int nt = 0; nt < NT; nt++)
                    mma_tf32(acc[mt][nt], af[mt], bf[nt]);
        }
    }

    const float g = gainPtr ? *gainPtr : 1.0f;
    float sk = 0.f;
    if (EPI == 2) sk = *skipPtr;
    const int r = lane >> 2, c = lane & 3;
#pragma unroll
    for (int mt = 0; mt < MT; mt++) {
        int row0 = by * BM + (wm * MT + mt) * 16 + r;
        float g0 = g, g1 = g;
        if (SCALE) { g0 = g * rs[row0]; g1 = g * rs[row0 + 8]; }
#pragma unroll
        for (int nt = 0; nt < NT; nt++) {
            int col = bx * BN + (wn * NT + nt) * 8 + c * 2;
            size_t i0 = (size_t)row0 * N + col;
            size_t i1 = (size_t)(row0 + 8) * N + col;
            float2 v0 = make_float2(g0 * acc[mt][nt][0], g0 * acc[mt][nt][1]);
            float2 v1 = make_float2(g1 * acc[mt][nt][2], g1 * acc[mt][nt][3]);
            if (EPI >= 1) {
                float2 r0 = *(const float2*)(res + i0);
                float2 r1 = *(const float2*)(res + i1);
                v0.x += r0.x; v0.y += r0.y;
                v1.x += r1.x; v1.y += r1.y;
            }
            if (EPI == 2) {
                float2 e0 = *(const float2*)(res2 + i0);
                float2 e1 = *(const float2*)(res2 + i1);
                v0.x += sk * e0.x; v0.y += sk * e0.y;
                v1.x += sk * e1.x; v1.y += sk * e1.y;
            }
            *(float2*)(C + i0) = v0;
            *(float2*)(C + i1) = v1;
        }
    }
}

template <int BM, int BN, int EPI, bool SCALE, int MINB>
__global__ void __launch_bounds__(256, MINB)
gemm4k(const float* __restrict__ A, const float* __restrict__ B,
       float* __restrict__ C, int N, int K,
       const float* __restrict__ res, const float* __restrict__ gainPtr,
       const float* __restrict__ res2, const float* __restrict__ skipPtr,
       const float* __restrict__ rs) {
    gemm4_body<BM, BN, EPI, SCALE>(A, B, C, N, K, res, gainPtr, res2, skipPtr,
                                   rs, blockIdx.x, blockIdx.y);
}

// fused Q/K/V, 128x64 tiles (384 blocks -> full chip); rs in epilogue
__global__ void __launch_bounds__(256, 2)
qkv4(const float* __restrict__ A,
     const float* __restrict__ Wq, const float* __restrict__ Wk,
     const float* __restrict__ Wv, const float* __restrict__ rs,
     float* __restrict__ Cq, float* __restrict__ Ck, float* __restrict__ Cv) {
    const float* B;
    float* C;
    if (blockIdx.z == 0)      { B = Wq; C = Cq; }
    else if (blockIdx.z == 1) { B = Wk; C = Ck; }
    else                      { B = Wv; C = Cv; }
    gemm4_body<128, 64, 0, true>(A, B, C, D, D, nullptr, nullptr, nullptr,
                                 nullptr, rs, blockIdx.x, blockIdx.y);
}

// ---------------- fused gate+linear+silu, BM=128/BN=64 per matrix -----------
__global__ void __launch_bounds__(256, 2)
gl5(const float* __restrict__ A,
    const float* __restrict__ Wg, const float* __restrict__ Wl,
    float* __restrict__ Ch, const float* __restrict__ rs) {
    constexpr int BM = 128, BN = 64;
    constexpr int WN = 4;
    constexpr int MT = 4, NT = 2;
    constexpr int LDR = 36;
    constexpr int STG_A = BM * LDR;
    constexpr int STG_B = BN * LDR;
    constexpr int STG = STG_A + 2 * STG_B;
    const int K = D, N = DFF;

    extern __shared__ float sm[];
    const int tid = threadIdx.x, warp = tid >> 5, lane = tid & 31;
    const int wm = warp / WN, wn = warp % WN;
    const int lr = tid >> 3, lc = (tid & 7) << 2;
    const int bx = blockIdx.x, by = blockIdx.y;

    const float* Ab = A  + (size_t)(by * BM + lr) * K + lc;
    const float* Gb = Wg + (size_t)(bx * BN + lr) * K + lc;
    const float* Lb = Wl + (size_t)(bx * BN + lr) * K + lc;
    const uint32_t smb = (uint32_t)__cvta_generic_to_shared(sm);
    const uint32_t d0 = smb + (uint32_t)(lr * LDR + lc) * 4u;

    auto issue = [&](int tile, int stg) {
        uint32_t base = d0 + (uint32_t)(stg * STG) * 4u;
#pragma unroll
        for (int i = 0; i < 4; i++)
            cp16(base + i * 32 * LDR * 4, Ab + (size_t)tile * 32 + (size_t)i * 32 * K);
#pragma unroll
        for (int i = 0; i < 2; i++) {
            cp16(base + (STG_A + i * 32 * LDR) * 4,         Gb + (size_t)tile * 32 + (size_t)i * 32 * K);
            cp16(base + (STG_A + STG_B + i * 32 * LDR) * 4, Lb + (size_t)tile * 32 + (size_t)i * 32 * K);
        }
        CP_COMMIT();
    };

    float accg[MT][NT][4], accl[MT][NT][4];
#pragma unroll
    for (int mt = 0; mt < MT; mt++)
#pragma unroll
        for (int nt = 0; nt < NT; nt++)
#pragma unroll
            for (int i = 0; i < 4; i++) { accg[mt][nt][i] = 0.f; accl[mt][nt][i] = 0.f; }

    issue(0, 0);
    issue(1, 1);

    const int ntiles = K >> 5;
    const int abase0 = (wm * MT * 16 + (lane >> 2)) * LDR + (lane & 3);
    const int bbase0 = (wn * NT * 8  + (lane >> 2)) * LDR + (lane & 3);

    for (int t = 0; t < ntiles; t++) {
        if (t + 1 < ntiles) { CP_WAIT1(); } else { CP_WAIT0(); }
        __syncthreads();
        if (t + 2 < ntiles) issue(t + 2, (t + 2) % 3);

        const float* as = sm + (t % 3) * STG;
        const float* gs = as + STG_A;
        const float* ls = gs + STG_B;
#pragma unroll
        for (int kk = 0; kk < 4; kk++) {
            uint32_t af[MT][4];
#pragma unroll
            for (int mt = 0; mt < MT; mt++) {
                int o = abase0 + mt * 16 * LDR + kk * 8;
                af[mt][0] = f2tf(as[o]);
                af[mt][1] = f2tf(as[o + 8 * LDR]);
                af[mt][2] = f2tf(as[o + 4]);
                af[mt][3] = f2tf(as[o + 8 * LDR + 4]);
            }
            uint32_t gf[NT][2], lf[NT][2];
#pragma unroll
            for (int nt = 0; nt < NT; nt++) {
                int o = bbase0 + nt * 8 * LDR + kk * 8;
                gf[nt][0] = f2tf(gs[o]); gf[nt][1] = f2tf(gs[o + 4]);
                lf[nt][0] = f2tf(ls[o]); lf[nt][1] = f2tf(ls[o + 4]);
            }
#pragma unroll
            for (int mt = 0; mt < MT; mt++)
#pragma unroll
                for (int nt = 0; nt < NT; nt++) {
                    mma_tf32(accg[mt][nt], af[mt], gf[nt]);
                    mma_tf32(accl[mt][nt], af[mt], lf[nt]);
                }
        }
    }

    const int r = lane >> 2, c = lane & 3;
#pragma unroll
    for (int mt = 0; mt < MT; mt++) {
        int row0 = by * BM + (wm * MT + mt) * 16 + r;
        float s0 = rs[row0], s1 = rs[row0 + 8];
#pragma unroll
        for (int nt = 0; nt < NT; nt++) {
            int col = bx * BN + (wn * NT + nt) * 8 + c * 2;
#pragma unroll
            for (int half = 0; half < 2; half++) {
                size_t idx = (size_t)(row0 + half * 8) * N + col;
                float s = half ? s1 : s0;
                float gv0 = accg[mt][nt][half * 2 + 0] * s;
                float gv1 = accg[mt][nt][half * 2 + 1] * s;
                float lv0 = accl[mt][nt][half * 2 + 0] * s;
                float lv1 = accl[mt][nt][half * 2 + 1] * s;
                float h0 = gv0 / (1.0f + expf(-gv0)) * lv0;
                float h1 = gv1 / (1.0f + expf(-gv1)) * lv1;
                *(float2*)(Ch + idx) = make_float2(h0, h1);
            }
        }
    }
}

// ---------------- fused causal attention (online softmax, exact fp32) -------
// Softmax update parallelized: 4 threads per q-row, shfl reductions.
__global__ void __launch_bounds__(256)
attn_kernel(const float* __restrict__ q, const float* __restrict__ k,
            const float* __restrict__ v, float* __restrict__ y) {
    const int h  = blockIdx.x;
    const int q0 = blockIdx.y * 64;
    __shared__ float Qs[64][64];
    __shared__ float Ks[64][32];
    __shared__ float Vs[32][64];
    __shared__ float Ss[64][33];
    __shared__ float mS[64], lS[64], aS[64];
    int tid = threadIdx.x;
    int tx = tid & 15, ty = tid >> 4;

    {
        int r  = tid >> 2;
        int d0 = (tid & 3) << 4;
        const float* src = q + (size_t)(q0 + r) * D + h * HD + d0;
#pragma unroll
        for (int i = 0; i < 16; i += 4) {
            float4 t4 = *(const float4*)(src + i);
            Qs[d0 + i + 0][r] = t4.x; Qs[d0 + i + 1][r] = t4.y;
            Qs[d0 + i + 2][r] = t4.z; Qs[d0 + i + 3][r] = t4.w;
        }
    }
    if (tid < 64) { mS[tid] = NEGF; lS[tid] = 0.f; }
    float acc[4][4];
#pragma unroll
    for (int i = 0; i < 4; i++)
#pragma unroll
        for (int jj = 0; jj < 4; jj++) acc[i][jj] = 0.f;
    __syncthreads();

    const int srow  = tid >> 2;          // softmax row (0..63)
    const int spart = tid & 3;           // 8-entry slice
    const int nk = q0 + 64;
    for (int k0 = 0; k0 < nk; k0 += 32) {
        {
            int kr = tid >> 3;
            int d0 = (tid & 7) << 3;
            const float* ks = k + (size_t)(k0 + kr) * D + h * HD + d0;
            float4 t0 = *(const float4*)ks;
            float4 t1 = *(const float4*)(ks + 4);
            Ks[d0 + 0][kr] = t0.x; Ks[d0 + 1][kr] = t0.y; Ks[d0 + 2][kr] = t0.z; Ks[d0 + 3][kr] = t0.w;
            Ks[d0 + 4][kr] = t1.x; Ks[d0 + 5][kr] = t1.y; Ks[d0 + 6][kr] = t1.z; Ks[d0 + 7][kr] = t1.w;
            const float* vsp = v + (size_t)(k0 + kr) * D + h * HD + d0;
            *(float4*)&Vs[kr][d0]     = *(const float4*)vsp;
            *(float4*)&Vs[kr][d0 + 4] = *(const float4*)(vsp + 4);
        }
        __syncthreads();

        float sc[4][2];
#pragma unroll
        for (int i = 0; i < 4; i++) { sc[i][0] = 0.f; sc[i][1] = 0.f; }
#pragma unroll 16
        for (int d = 0; d < 64; d++) {
            float4 qa = *(const float4*)&Qs[d][ty << 2];
            float2 kb = *(const float2*)&Ks[d][tx << 1];
            sc[0][0] = fmaf(qa.x, kb.x, sc[0][0]); sc[0][1] = fmaf(qa.x, kb.y, sc[0][1]);
            sc[1][0] = fmaf(qa.y, kb.x, sc[1][0]); sc[1][1] = fmaf(qa.y, kb.y, sc[1][1]);
            sc[2][0] = fmaf(qa.z, kb.x, sc[2][0]); sc[2][1] = fmaf(qa.z, kb.y, sc[2][1]);
            sc[3][0] = fmaf(qa.w, kb.x, sc[3][0]); sc[3][1] = fmaf(qa.w, kb.y, sc[3][1]);
        }
#pragma unroll
        for (int i = 0; i < 4; i++) {
            int qg = q0 + (ty << 2) + i;
#pragma unroll
            for (int jj = 0; jj < 2; jj++) {
                int kg = k0 + (tx << 1) + jj;
                float val = sc[i][jj] * 0.125f;
                if (kg > qg) val = NEGF;
                Ss[(ty << 2) + i][(tx << 1) + jj] = val;
            }
        }
        __syncthreads();

        // online softmax update: 4 threads per row, 8 entries each
        {
            float mo = mS[srow];
            float mx = mo;
#pragma unroll
            for (int jj = 0; jj < 8; jj++)
                mx = fmaxf(mx, Ss[srow][spart * 8 + jj]);
            mx = fmaxf(mx, __shfl_xor_sync(0xffffffffu, mx, 1));
            mx = fmaxf(mx, __shfl_xor_sync(0xffffffffu, mx, 2));
            float sum = 0.f;
#pragma unroll
            for (int jj = 0; jj < 8; jj++) {
                float pp = expf(Ss[srow][spart * 8 + jj] - mx);
                Ss[srow][spart * 8 + jj] = pp;
                sum += pp;
            }
            sum += __shfl_xor_sync(0xffffffffu, sum, 1);
            sum += __shfl_xor_sync(0xffffffffu, sum, 2);
            if (spart == 0) {
                float al = expf(mo - mx);
                lS[srow] = lS[srow] * al + sum;
                mS[srow] = mx;
                aS[srow] = al;
            }
        }
        __syncthreads();

#pragma unroll
        for (int i = 0; i < 4; i++) {
            float al = aS[(ty << 2) + i];
#pragma unroll
            for (int jj = 0; jj < 4; jj++) acc[i][jj] *= al;
        }
#pragma unroll 8
        for (int kk = 0; kk < 32; kk++) {
            float4 vb = *(const float4*)&Vs[kk][tx << 2];
            float p0 = Ss[(ty << 2) + 0][kk];
            float p1 = Ss[(ty << 2) + 1][kk];
            float p2 = Ss[(ty << 2) + 2][kk];
            float p3 = Ss[(ty << 2) + 3][kk];
            acc[0][0] = fmaf(p0, vb.x, acc[0][0]); acc[0][1] = fmaf(p0, vb.y, acc[0][1]);
            acc[0][2] = fmaf(p0, vb.z, acc[0][2]); acc[0][3] = fmaf(p0, vb.w, acc[0][3]);
            acc[1][0] = fmaf(p1, vb.x, acc[1][0]); acc[1][1] = fmaf(p1, vb.y, acc[1][1]);
            acc[1][2] = fmaf(p1, vb.z, acc[1][2]); acc[1][3] = fmaf(p1, vb.w, acc[1][3]);
            acc[2][0] = fmaf(p2, vb.x, acc[2][0]); acc[2][1] = fmaf(p2, vb.y, acc[2][1]);
            acc[2][2] = fmaf(p2, vb.z, acc[2][2]); acc[2][3] = fmaf(p2, vb.w, acc[2][3]);
            acc[3][0] = fmaf(p3, vb.x, acc[3][0]); acc[3][1] = fmaf(p3, vb.y, acc[3][1]);
            acc[3][2] = fmaf(p3, vb.z, acc[3][2]); acc[3][3] = fmaf(p3, vb.w, acc[3][3]);
        }
        __syncthreads();
    }

#pragma unroll
    for (int i = 0; i < 4; i++) {
        float linv = 1.0f / lS[(ty << 2) + i];
        float4 o = make_float4(acc[i][0] * linv, acc[i][1] * linv,
                               acc[i][2] * linv, acc[i][3] * linv);
        *(float4*)(y + (size_t)(q0 + (ty << 2) + i) * D + h * HD + (tx << 2)) = o;
    }
}

// ---------------- launch -----------------------------------------------------
extern "C" void kernel_launch(void* const* d_in, const int* in_sizes, int n_in,
                              void* d_out, int out_size) {
    const int*   ids          = (const int*)  d_in[0];
    const float* embed        = (const float*)d_in[1];
    const float* Wq           = (const float*)d_in[2];
    const float* Wk           = (const float*)d_in[3];
    const float* Wv           = (const float*)d_in[4];
    const float* Wo           = (const float*)d_in[5];
    const float* head_gain    = (const float*)d_in[6];
    const float* attn_gain    = (const float*)d_in[7];
    const float* Wg           = (const float*)d_in[8];
    const float* Wl           = (const float*)d_in[9];
    const float* Wr           = (const float*)d_in[10];
    const float* mlp_gain     = (const float*)d_in[11];
    const float* embed_skip   = (const float*)d_in[12];
    const float* lm_head      = (const float*)d_in[13];
    const float* lm_head_gain = (const float*)d_in[14];
    float* out = (float*)d_out;

    float *px, *pex, *pq, *pk, *pv, *py, *ph1, *prs;
    cudaGetSymbolAddress((void**)&px,  g_x);
    cudaGetSymbolAddress((void**)&pex, g_ex);
    cudaGetSymbolAddress((void**)&pq,  g_q);
    cudaGetSymbolAddress((void**)&pk,  g_k);
    cudaGetSymbolAddress((void**)&pv,  g_v);
    cudaGetSymbolAddress((void**)&py,  g_y);
    cudaGetSymbolAddress((void**)&ph1, g_h1);
    cudaGetSymbolAddress((void**)&prs, g_rs);

    const int SM_Q  = 3 * (128 + 64)  * 36 * 4;   // 82944
    const int SM_S  = 3 * (64 + 64)   * 36 * 4;   // 55296
    const int SM_GL = 3 * (128 + 128) * 36 * 4;   // 110592
    const int SM_LM = 3 * (128 + 128) * 36 * 4;   // 110592

    cudaFuncSetAttribute(qkv4, cudaFuncAttributeMaxDynamicSharedMemorySize, SM_Q);
    cudaFuncSetAttribute(gl5,  cudaFuncAttributeMaxDynamicSharedMemorySize, SM_GL);
    cudaFuncSetAttribute(gemm4k<64, 64, 1, false, 3>, cudaFuncAttributeMaxDynamicSharedMemorySize, SM_S);
    cudaFuncSetAttribute(gemm4k<64, 64, 2, false, 3>, cudaFuncAttributeMaxDynamicSharedMemorySize, SM_S);
    cudaFuncSetAttribute(gemm4k<128, 128, 0, true, 2>, cudaFuncAttributeMaxDynamicSharedMemorySize, SM_LM);

    rope_table_kernel<<<(SEQ * 32) / 256, 256>>>();
    embed_rms_kernel<<<SEQ, 256>>>(ids, embed, px, pex);

    dim3 gQKV(D / 64, SEQ / 128, 3);       // 384 blocks
    dim3 gOW (D / 64, SEQ / 64);           // 256 blocks
    dim3 gGL (DFF / 64, SEQ / 128);        // 512 blocks
    dim3 gLM (VOC / 128, SEQ / 128);       // 2000 blocks
    dim3 gRope(SEQ, H, 2);
    dim3 gAttn(H, SEQ / 64);

    for (int l = 0; l < LYR; l++) {
        rs_kernel<<<SEQ, 256>>>(px, prs);
        qkv4<<<gQKV, 256, SM_Q>>>(px, Wq + (size_t)l * D * D, Wk + (size_t)l * D * D,
                                  Wv + (size_t)l * D * D, prs, pq, pk, pv);
        rope_rms_kernel<<<gRope, 64>>>(pq, pk, head_gain, l);
        attn_kernel<<<gAttn, 256>>>(pq, pk, pv, py);
        gemm4k<64, 64, 1, false, 3><<<gOW, 256, SM_S>>>(
            py, Wo + (size_t)l * D * D, px, D, D, px, attn_gain + l,
            nullptr, nullptr, nullptr);
        rs_kernel<<<SEQ, 256>>>(px, prs);
        gl5<<<gGL, 256, SM_GL>>>(px, Wg + (size_t)l * DFF * D,
                                 Wl + (size_t)l * DFF * D, ph1, prs);
        gemm4k<64, 64, 2, false, 3><<<gOW, 256, SM_S>>>(
            ph1, Wr + (size_t)l * D * DFF, px, D, DFF, px, mlp_gain + l,
            pex, embed_skip + l, nullptr);
    }

    rs_kernel<<<SEQ, 256>>>(px, prs);
    gemm4k<128, 128, 0, true, 2><<<gLM, 256, SM_LM>>>(
        px, lm_head, out, VOC, D, nullptr, lm_head_gain, nullptr, nullptr, prs);
}